// round 1
// baseline (speedup 1.0000x reference)
#include <cuda_runtime.h>
#include <math.h>
#include <stdint.h>

#define NXI 512
#define LDIM 128
#define NSTATES 128
#define NIN 64
#define HDIM 1152           // 2*NXI + LDIM
#define BATCHN 32768
#define EPSV 0.001f
#define NEWTON_ITERS 22

// ---------------- device scratch (static allocation; no cudaMalloc) ----------------
__device__ float g_H[HDIM * HDIM];
__device__ float g_E[NXI * NXI];
__device__ float g_Za[NXI * NXI];
__device__ float g_Zb[NXI * NXI];
__device__ float g_T[NXI * NXI];
__device__ float g_R[NXI * 768];          // [Fm | B1 | B2]
__device__ float g_Wpre[LDIM * 640];      // [-H21 | D12]
__device__ float g_Wout[576 * 768];       // rows 0..63: [C2|D21|D22]; rows 64..575: Einv*[Fm|B1|B2]
__device__ float g_D11[LDIM * LDIM];
__device__ float g_LamInv[LDIM];
__device__ float g_rows[NXI];
__device__ float g_fro2inv;
__device__ float g_pre[(size_t)BATCHN * LDIM];
__device__ float g_eps[(size_t)BATCHN * LDIM];

// ---------------- generic small GEMM: C = op(A) * op(B), 64x64x16 tiles ----------------
// TA: A is (K x M), access A[k*lda+m]. else A is (M x K): A[m*lda+k].
// TB: B is (N x K), access B[n*ldb+k]. else B is (K x N): B[k*ldb+n].
// emode 0: C = acc ; 1: C = 2*D - acc (Newton) ; 2: C = acc + EPSV on diagonal
template <bool TA, bool TB>
__global__ __launch_bounds__(256) void gemm64(const float* __restrict__ A,
                                              const float* __restrict__ B,
                                              float* __restrict__ C,
                                              int M, int N, int K,
                                              int lda, int ldb, int ldc,
                                              const float* __restrict__ D, int emode) {
    __shared__ float As[16][65];
    __shared__ float Bs[16][65];
    int tid = threadIdx.x;
    int tx = tid & 15, ty = tid >> 4;
    int m0 = blockIdx.y * 64, n0 = blockIdx.x * 64;
    float acc[4][4] = {};
    for (int k0 = 0; k0 < K; k0 += 16) {
        __syncthreads();
#pragma unroll
        for (int r = 0; r < 4; ++r) {
            int idx = tid + r * 256;
            if (TA) {
                int k = idx >> 6, m = idx & 63;
                As[k][m] = A[(size_t)(k0 + k) * lda + m0 + m];
            } else {
                int m = idx >> 4, k = idx & 15;
                As[k][m] = A[(size_t)(m0 + m) * lda + k0 + k];
            }
            if (TB) {
                int n = idx >> 4, k = idx & 15;
                Bs[k][n] = B[(size_t)(n0 + n) * ldb + k0 + k];
            } else {
                int k = idx >> 6, n = idx & 63;
                Bs[k][n] = B[(size_t)(k0 + k) * ldb + n0 + n];
            }
        }
        __syncthreads();
#pragma unroll
        for (int k = 0; k < 16; ++k) {
            float av[4], bv[4];
#pragma unroll
            for (int i = 0; i < 4; ++i) av[i] = As[k][ty * 4 + i];
#pragma unroll
            for (int j = 0; j < 4; ++j) bv[j] = Bs[k][tx * 4 + j];
#pragma unroll
            for (int i = 0; i < 4; ++i)
#pragma unroll
                for (int j = 0; j < 4; ++j) acc[i][j] = fmaf(av[i], bv[j], acc[i][j]);
        }
    }
#pragma unroll
    for (int i = 0; i < 4; ++i) {
        int m = m0 + ty * 4 + i;
#pragma unroll
        for (int j = 0; j < 4; ++j) {
            int n = n0 + tx * 4 + j;
            float v = acc[i][j];
            if (emode == 1) v = 2.0f * D[(size_t)m * ldc + n] - v;
            else if (emode == 2 && m == n) v += EPSV;
            C[(size_t)m * ldc + n] = v;
        }
    }
}

// ---------------- batch GEMM: out(M x N) = [A0|A1|A2](M x Ktot) * W(N x Ktot)^T ----------------
// 128x64 block tile, BK=16, 256 threads, 8x4 per-thread tile.
__global__ __launch_bounds__(256) void gemm_batch(
    const float* __restrict__ A0, const float* __restrict__ A1, const float* __restrict__ A2,
    int K0, int K01, int Ktot,
    const float* __restrict__ W, int N,
    float* __restrict__ out0, float* __restrict__ out1, int mode) {
    __shared__ float As[16][132];
    __shared__ float Bs[16][68];
    int tid = threadIdx.x;
    int m0 = blockIdx.y * 128;
    int n0 = blockIdx.x * 64;
    int tx = tid & 15, ty = tid >> 4;
    int lr = tid >> 2, lq = tid & 3;
    float acc[8][4] = {};
    for (int k0 = 0; k0 < Ktot; k0 += 16) {
        const float* Ap; int lda, kb;
        if (k0 < K0)        { Ap = A0; lda = K0;         kb = k0; }
        else if (k0 < K01)  { Ap = A1; lda = K01 - K0;   kb = k0 - K0; }
        else                { Ap = A2; lda = Ktot - K01; kb = k0 - K01; }
        float4 a0 = *(const float4*)(Ap + (size_t)(m0 + lr) * lda + kb + lq * 4);
        float4 a1 = *(const float4*)(Ap + (size_t)(m0 + lr + 64) * lda + kb + lq * 4);
        float4 bw = *(const float4*)(W + (size_t)(n0 + lr) * Ktot + k0 + lq * 4);
        __syncthreads();
        As[lq * 4 + 0][lr] = a0.x; As[lq * 4 + 1][lr] = a0.y;
        As[lq * 4 + 2][lr] = a0.z; As[lq * 4 + 3][lr] = a0.w;
        As[lq * 4 + 0][lr + 64] = a1.x; As[lq * 4 + 1][lr + 64] = a1.y;
        As[lq * 4 + 2][lr + 64] = a1.z; As[lq * 4 + 3][lr + 64] = a1.w;
        Bs[lq * 4 + 0][lr] = bw.x; Bs[lq * 4 + 1][lr] = bw.y;
        Bs[lq * 4 + 2][lr] = bw.z; Bs[lq * 4 + 3][lr] = bw.w;
        __syncthreads();
#pragma unroll
        for (int k = 0; k < 16; ++k) {
            float4 av0 = *(const float4*)&As[k][ty * 8];
            float4 av1 = *(const float4*)&As[k][ty * 8 + 4];
            float4 bv = *(const float4*)&Bs[k][tx * 4];
            float a[8] = {av0.x, av0.y, av0.z, av0.w, av1.x, av1.y, av1.z, av1.w};
            float b[4] = {bv.x, bv.y, bv.z, bv.w};
#pragma unroll
            for (int i = 0; i < 8; ++i)
#pragma unroll
                for (int j = 0; j < 4; ++j) acc[i][j] = fmaf(a[i], b[j], acc[i][j]);
        }
    }
#pragma unroll
    for (int i = 0; i < 8; ++i) {
        int m = m0 + ty * 8 + i;
#pragma unroll
        for (int j = 0; j < 4; ++j) {
            int n = n0 + tx * 4 + j;
            float v = acc[i][j];
            if (mode == 0) {
                out0[(size_t)m * N + n] = v;
            } else {
                if (n < NIN) out0[(size_t)m * NIN + n] = v;
                else out1[(size_t)m * NXI + (n - NIN)] = v;
            }
        }
    }
}

// ---------------- parameter builders ----------------
__global__ void build_E(const float* __restrict__ Y) {
    int idx = blockIdx.x * blockDim.x + threadIdx.x;
    if (idx >= NXI * NXI) return;
    int i = idx >> 9, j = idx & 511;
    g_E[idx] = 0.5f * (g_H[(size_t)i * HDIM + j] + g_H[(size_t)(640 + i) * HDIM + 640 + j] +
                       Y[(size_t)i * NXI + j] - Y[(size_t)j * NXI + i]);
}
__global__ void build_Wpre(const float* __restrict__ D12) {
    int idx = blockIdx.x * blockDim.x + threadIdx.x;
    if (idx >= LDIM * 640) return;
    int r = idx / 640, c = idx - r * 640;
    g_Wpre[idx] = (c < NXI) ? -g_H[(size_t)(NXI + r) * HDIM + c]
                            : D12[r * NSTATES + (c - NXI)];
}
__global__ void build_D11() {
    int idx = blockIdx.x * blockDim.x + threadIdx.x;
    if (idx >= LDIM * LDIM) return;
    int i = idx >> 7, j = idx & 127;
    g_D11[idx] = (j < i) ? -g_H[(size_t)(NXI + i) * HDIM + NXI + j] : 0.0f;
    if (j == i) g_LamInv[i] = 2.0f / g_H[(size_t)(NXI + i) * HDIM + NXI + i];
}
__global__ void build_R(const float* __restrict__ B2) {
    int idx = blockIdx.x * blockDim.x + threadIdx.x;
    if (idx >= NXI * 768) return;
    int i = idx / 768, c = idx - i * 768;
    g_R[idx] = (c < 640) ? g_H[(size_t)(640 + i) * HDIM + c] : B2[i * NSTATES + (c - 640)];
}
__global__ void build_WoutTop(const float* __restrict__ C2, const float* __restrict__ D21,
                              const float* __restrict__ D22) {
    int idx = blockIdx.x * blockDim.x + threadIdx.x;
    if (idx >= NIN * 768) return;
    int r = idx / 768, c = idx - r * 768;
    g_Wout[idx] = (c < NXI) ? C2[r * NXI + c]
                            : (c < 640 ? D21[r * LDIM + (c - NXI)] : D22[r * NSTATES + (c - 640)]);
}

// ---------------- deterministic Frobenius norm + Newton init ----------------
__global__ void rowsq_kernel() {
    int i = blockIdx.x;
    float s = 0.0f;
    for (int j = threadIdx.x; j < NXI; j += 256) {
        float v = g_E[(size_t)i * NXI + j];
        s = fmaf(v, v, s);
    }
    __shared__ float red[256];
    red[threadIdx.x] = s;
    __syncthreads();
    for (int o = 128; o > 0; o >>= 1) {
        if (threadIdx.x < o) red[threadIdx.x] += red[threadIdx.x + o];
        __syncthreads();
    }
    if (threadIdx.x == 0) g_rows[i] = red[0];
}
__global__ void finfro_kernel() {
    __shared__ float red[512];
    red[threadIdx.x] = g_rows[threadIdx.x];
    __syncthreads();
    for (int o = 256; o > 0; o >>= 1) {
        if (threadIdx.x < o) red[threadIdx.x] += red[threadIdx.x + o];
        __syncthreads();
    }
    if (threadIdx.x == 0) g_fro2inv = 1.0f / red[0];
}
__global__ void initZ_kernel() {
    int idx = blockIdx.x * blockDim.x + threadIdx.x;
    if (idx >= NXI * NXI) return;
    int i = idx >> 9, j = idx & 511;
    g_Za[idx] = g_E[(size_t)j * NXI + i] * g_fro2inv;
}

// ---------------- tanh forward-substitution scan ----------------
// eps[b,i] = tanh( (pre[b,i] + sum_{j<i} eps[b,j]*D11[i,j]) / Lam[i] )
__global__ __launch_bounds__(64) void eps_kernel() {
    __shared__ float es[128 * 64];
    __shared__ float li[128];
    int tid = threadIdx.x;
    size_t b = (size_t)blockIdx.x * 64 + tid;
    for (int i = tid; i < 128; i += 64) li[i] = g_LamInv[i];
    __syncthreads();
    for (int i = 0; i < 128; ++i) {
        float v = g_pre[b * 128 + i];
        const float* __restrict__ dr = &g_D11[i * 128];
        float v0 = 0.f, v1 = 0.f, v2 = 0.f, v3 = 0.f;
        int j = 0;
        for (; j + 3 < i; j += 4) {
            v0 = fmaf(es[(j + 0) * 64 + tid], dr[j + 0], v0);
            v1 = fmaf(es[(j + 1) * 64 + tid], dr[j + 1], v1);
            v2 = fmaf(es[(j + 2) * 64 + tid], dr[j + 2], v2);
            v3 = fmaf(es[(j + 3) * 64 + tid], dr[j + 3], v3);
        }
        for (; j < i; ++j) v0 = fmaf(es[j * 64 + tid], dr[j], v0);
        v += (v0 + v1) + (v2 + v3);
        float e = tanhf(v * li[i]);
        es[i * 64 + tid] = e;
        g_eps[b * 128 + i] = e;
    }
}

// ---------------- launch ----------------
extern "C" void kernel_launch(void* const* d_in, const int* in_sizes, int n_in,
                              void* d_out, int out_size) {
    (void)in_sizes; (void)n_in;
    const float* w   = (const float*)d_in[1];
    const float* xi  = (const float*)d_in[2];
    const float* X   = (const float*)d_in[3];
    const float* Y   = (const float*)d_in[4];
    const float* B2  = (const float*)d_in[5];
    const float* C2  = (const float*)d_in[6];
    const float* D21 = (const float*)d_in[7];
    const float* D22 = (const float*)d_in[8];
    const float* D12 = (const float*)d_in[9];
    float* out   = (float*)d_out;
    float* out_u = out;                                 // (B,1,64)
    float* out_x = out + (size_t)BATCHN * NIN;          // (B,1,512)
    (void)out_size;

    float *pH, *pE, *pZa, *pZb, *pT, *pR, *pWout, *pWpre, *pPre, *pEps;
    cudaGetSymbolAddress((void**)&pH, g_H);
    cudaGetSymbolAddress((void**)&pE, g_E);
    cudaGetSymbolAddress((void**)&pZa, g_Za);
    cudaGetSymbolAddress((void**)&pZb, g_Zb);
    cudaGetSymbolAddress((void**)&pT, g_T);
    cudaGetSymbolAddress((void**)&pR, g_R);
    cudaGetSymbolAddress((void**)&pWout, g_Wout);
    cudaGetSymbolAddress((void**)&pWpre, g_Wpre);
    cudaGetSymbolAddress((void**)&pPre, g_pre);
    cudaGetSymbolAddress((void**)&pEps, g_eps);

    // 1) H = X^T X + eps*I
    gemm64<true, false><<<dim3(HDIM / 64, HDIM / 64), 256>>>(
        X, X, pH, HDIM, HDIM, HDIM, HDIM, HDIM, HDIM, nullptr, 2);

    // 2) derived parameter matrices
    build_E<<<(NXI * NXI + 255) / 256, 256>>>(Y);
    build_Wpre<<<(LDIM * 640 + 255) / 256, 256>>>(D12);
    build_D11<<<(LDIM * LDIM + 255) / 256, 256>>>();
    build_R<<<(NXI * 768 + 255) / 256, 256>>>(B2);
    build_WoutTop<<<(NIN * 768 + 255) / 256, 256>>>(C2, D21, D22);

    // 3) Newton-Schulz inverse of E: Z0 = E^T/||E||_F^2 ; Z <- 2Z - Z(EZ)
    rowsq_kernel<<<NXI, 256>>>();
    finfro_kernel<<<1, 512>>>();
    initZ_kernel<<<(NXI * NXI + 255) / 256, 256>>>();
    float* Zc = pZa;
    float* Zn = pZb;
    for (int it = 0; it < NEWTON_ITERS; ++it) {
        gemm64<false, false><<<dim3(8, 8), 256>>>(
            pE, Zc, pT, NXI, NXI, NXI, NXI, NXI, NXI, nullptr, 0);
        gemm64<false, false><<<dim3(8, 8), 256>>>(
            Zc, pT, Zn, NXI, NXI, NXI, NXI, NXI, NXI, Zc, 1);
        float* tmp = Zc; Zc = Zn; Zn = tmp;
    }

    // 4) Wout rows 64..575 = Einv @ [Fm|B1|B2]
    gemm64<false, false><<<dim3(768 / 64, NXI / 64), 256>>>(
        Zc, pR, pWout + 64 * 768, NXI, 768, NXI, NXI, 768, 768, nullptr, 0);

    // 5) pre = [xi|w] @ Wpre^T     (M=32768, N=128, K=640)
    gemm_batch<<<dim3(128 / 64, BATCHN / 128), 256>>>(
        xi, w, w, NXI, 640, 640, pWpre, 128, pPre, nullptr, 0);

    // 6) tanh forward substitution
    eps_kernel<<<BATCHN / 64, 64>>>();

    // 7) [u | xi_] = [xi|eps|w] @ Wout^T   (M=32768, N=576, K=768)
    gemm_batch<<<dim3(576 / 64, BATCHN / 128), 256>>>(
        xi, pEps, w, NXI, 640, 768, pWout, 576, out_u, out_x, 1);
}